// round 2
// baseline (speedup 1.0000x reference)
#include <cuda_runtime.h>
#include <cuda_bf16.h>

#define B_   32
#define N_   4096
#define D_   64
#define BC_  4
#define C_   129

// Scratch (no allocations allowed)
__device__ __align__(16) int   g_cl[BC_ * N_];       // normalized int32 cluster ids
__device__ __align__(16) int   g_order[BC_ * N_];
__device__ __align__(16) int   g_starts[BC_ * (C_ + 1)];
__device__ __align__(16) float g_Qc[B_ * C_ * D_];   // normalized centers
__device__ __align__(16) float g_Kc[B_ * C_ * D_];
__device__ __align__(16) float g_Vc[B_ * C_ * D_];
__device__ __align__(16) float g_Vout[B_ * C_ * D_];

// ---------------------------------------------------------------------------
// Kernel 0: dtype-robust normalization of cluster labels into g_cl.
// If the input is really int64 (all int64-reads in range), use it; otherwise
// the data is int32 (JAX x64-disabled silently downcasts .astype(int64)).
// ---------------------------------------------------------------------------
__global__ void prep_kernel(const void* __restrict__ cl_raw) {
    __shared__ int s_bad;
    if (threadIdx.x == 0) s_bad = 0;
    __syncthreads();
    const long long* c64 = (const long long*)cl_raw;
    int bad = 0;
    // First half of int64 view == entire buffer if data is int32.
    for (int i = threadIdx.x; i < (BC_ * N_) / 2; i += 256) {
        long long v = c64[i];
        if (v < 0 || v >= C_) bad = 1;
    }
    if (bad) atomicOr(&s_bad, 1);
    __syncthreads();
    if (s_bad) {
        const int* c32 = (const int*)cl_raw;
        for (int i = threadIdx.x; i < BC_ * N_; i += 256) g_cl[i] = c32[i];
    } else {
        for (int i = threadIdx.x; i < BC_ * N_; i += 256) g_cl[i] = (int)c64[i];
    }
}

// ---------------------------------------------------------------------------
// Kernel 1: counting sort of cluster labels per cluster-batch (4 blocks)
// ---------------------------------------------------------------------------
__global__ void sort_kernel() {
    __shared__ int hist[C_];
    __shared__ int offs[C_];
    int bc = blockIdx.x;
    int t  = threadIdx.x;
    for (int i = t; i < C_; i += 256) hist[i] = 0;
    __syncthreads();
    for (int n = t; n < N_; n += 256) {
        int c = g_cl[bc * N_ + n];
        atomicAdd(&hist[c], 1);
    }
    __syncthreads();
    if (t == 0) {
        int s = 0;
        for (int c = 0; c < C_; c++) {
            g_starts[bc * (C_ + 1) + c] = s;
            offs[c] = s;
            s += hist[c];
        }
        g_starts[bc * (C_ + 1) + C_] = s;
    }
    __syncthreads();
    for (int n = t; n < N_; n += 256) {
        int c = g_cl[bc * N_ + n];
        int p = atomicAdd(&offs[c], 1);
        g_order[bc * N_ + p] = n;
    }
}

// ---------------------------------------------------------------------------
// Kernel 2: per-cluster centers (normalized). Warp owns a cluster; 4-way
// pipelined gathered float2 loads, no atomics. grid (32,4) x 256.
// ---------------------------------------------------------------------------
__global__ void centers_kernel(const float* __restrict__ Q,
                               const float* __restrict__ K,
                               const float* __restrict__ V) {
    int b    = blockIdx.x;
    int bc   = b & 3;
    int wid  = threadIdx.x >> 5;
    int lane = threadIdx.x & 31;

    const float2* Qb = (const float2*)(Q + (size_t)b * N_ * D_);
    const float2* Kb = (const float2*)(K + (size_t)b * N_ * D_);
    const float2* Vb = (const float2*)(V + (size_t)b * N_ * D_);
    const int* ord = g_order + bc * N_;
    const int* sts = g_starts + bc * (C_ + 1);

    for (int c = blockIdx.y * 8 + wid; c < C_; c += 32) {
        int s0 = sts[c], s1 = sts[c + 1];
        float w = (s1 > s0) ? 1.0f / (float)(s1 - s0) : 0.0f;
        float2 aq = {0.f, 0.f}, ak = {0.f, 0.f}, av = {0.f, 0.f};

        for (int m = s0; m < s1; m += 4) {
            int   base = __ldg(ord + m);
            int   nn[4];
            float mk[4];
#pragma unroll
            for (int j = 0; j < 4; j++) {
                bool vld = (m + j) < s1;
                nn[j] = vld ? __ldg(ord + m + j) : base;
                mk[j] = vld ? 1.0f : 0.0f;
            }
            float2 q4[4], k4[4], v4[4];
#pragma unroll
            for (int j = 0; j < 4; j++) {
                size_t off = (size_t)nn[j] * (D_ / 2) + lane;
                q4[j] = Qb[off];
                k4[j] = Kb[off];
                v4[j] = Vb[off];
            }
#pragma unroll
            for (int j = 0; j < 4; j++) {
                aq.x += mk[j] * q4[j].x; aq.y += mk[j] * q4[j].y;
                ak.x += mk[j] * k4[j].x; ak.y += mk[j] * k4[j].y;
                av.x += mk[j] * v4[j].x; av.y += mk[j] * v4[j].y;
            }
        }
        size_t o = (size_t)(b * C_ + c) * (D_ / 2) + lane;
        ((float2*)g_Qc)[o] = make_float2(aq.x * w, aq.y * w);
        ((float2*)g_Kc)[o] = make_float2(ak.x * w, ak.y * w);
        ((float2*)g_Vc)[o] = make_float2(av.x * w, av.y * w);
    }
}

// ---------------------------------------------------------------------------
// Kernel 3: centered attention. grid (32, 9) x 256. q-tile of 16.
// ---------------------------------------------------------------------------
__global__ void attn_kernel(float* __restrict__ attn_out) {
    __shared__ __align__(16) float sKV[C_ * 65];    // Kn (stride 65) then Vn (stride 64)
    __shared__ __align__(16) float sP[16 * 132];    // scores -> probabilities
    __shared__ __align__(16) float sQ[16 * 64];     // Q tile; reused as reduce buf
    __shared__ float sCnt[C_];

    int b  = blockIdx.x;
    int bc = b & 3;
    int q0 = blockIdx.y * 16;
    int t  = threadIdx.x;

    const int* sts = g_starts + bc * (C_ + 1);
    for (int k = t; k < C_; k += 256) sCnt[k] = (float)(sts[k + 1] - sts[k]);

    const float* Kc = g_Kc + (size_t)b * C_ * D_;
    for (int i = t; i < C_ * D_; i += 256) {
        int k = i >> 6, d = i & 63;
        sKV[k * 65 + d] = Kc[i];
    }
    const float* Qc = g_Qc + (size_t)b * C_ * D_;
    for (int i = t; i < 16 * 64; i += 256) {
        int j = i >> 6, q = q0 + j;
        sQ[i] = (q < C_) ? Qc[q * 64 + (i & 63)] : 0.0f;
    }
    __syncthreads();

    // Phase A: raw scores, 2-way q register blocking
    if (t < C_) {
        const float* kr = &sKV[t * 65];
#pragma unroll
        for (int jp = 0; jp < 8; jp++) {
            float sa = 0.f, sb = 0.f;
#pragma unroll
            for (int d = 0; d < 64; d++) {
                float kv = kr[d];
                sa += sQ[(2 * jp) * 64 + d] * kv;
                sb += sQ[(2 * jp + 1) * 64 + d] * kv;
            }
            sP[(2 * jp) * 132 + t]     = sa;
            sP[(2 * jp + 1) * 132 + t] = sb;
        }
    }
    __syncthreads();

    // Softmax with count reweighting: one warp per q row
    int wid = t >> 5, lane = t & 31;
    for (int j = wid; j < 16; j += 8) {
        float* row = &sP[j * 132];
        float v[5];
        float mx = -1e30f;
#pragma unroll
        for (int i = 0; i < 5; i++) {
            int k = lane + 32 * i;
            v[i] = (k < C_) ? row[k] : -1e30f;
            mx = fmaxf(mx, v[i]);
        }
#pragma unroll
        for (int o = 16; o; o >>= 1) mx = fmaxf(mx, __shfl_xor_sync(0xFFFFFFFFu, mx, o));
        float e[5];
        float sum = 0.f;
#pragma unroll
        for (int i = 0; i < 5; i++) {
            int k = lane + 32 * i;
            e[i] = (k < C_) ? __expf(v[i] - mx) * sCnt[k] : 0.0f;
            sum += e[i];
        }
#pragma unroll
        for (int o = 16; o; o >>= 1) sum += __shfl_xor_sync(0xFFFFFFFFu, sum, o);
        float inv = 1.0f / sum;
#pragma unroll
        for (int i = 0; i < 5; i++) {
            int k = lane + 32 * i;
            if (k < C_) row[k] = e[i] * inv;
        }
        if (lane == 0 && (q0 + j) < C_) attn_out[b * C_ + q0 + j] = e[0] * inv;
    }
    __syncthreads();

    // Load Vn (stride 64, float4-friendly)
    const float* Vc = g_Vc + (size_t)b * C_ * D_;
    for (int i = t; i < C_ * D_; i += 256) sKV[i] = Vc[i];
    __syncthreads();

    // Phase B: out[j][d] = sum_k p[j][k] * Vn[k][d]; 16 k-partitions x 16 float4 lanes
    const float4* Vn4  = (const float4*)sKV;
    float4*       red4 = (float4*)sQ;       // 16 x 16 float4
    int part = t >> 4, dv = t & 15;
    int nj = (C_ - q0 < 16) ? (C_ - q0) : 16;
    for (int j = 0; j < nj; j++) {
        float4 acc = {0.f, 0.f, 0.f, 0.f};
        for (int k = part; k < C_; k += 16) {
            float  p  = sP[j * 132 + k];
            float4 vv = Vn4[k * 16 + dv];
            acc.x += p * vv.x; acc.y += p * vv.y;
            acc.z += p * vv.z; acc.w += p * vv.w;
        }
        red4[part * 16 + dv] = acc;
        __syncthreads();
        if (part == 0) {
            float4 s = red4[dv];
#pragma unroll
            for (int pp = 1; pp < 16; pp++) {
                float4 r = red4[pp * 16 + dv];
                s.x += r.x; s.y += r.y; s.z += r.z; s.w += r.w;
            }
            ((float4*)(g_Vout + (size_t)(b * C_ + q0 + j) * D_))[dv] = s;
        }
        __syncthreads();
    }
}

// ---------------------------------------------------------------------------
// Kernel 4: gather broadcast out[b,n,:] = Vout[b, g_cl[b%4, n], :]
// ---------------------------------------------------------------------------
__global__ void gather_kernel(float* __restrict__ out) {
    int idx = blockIdx.x * 256 + threadIdx.x;   // over B*N*(D/4) float4s
    int dv  = idx & 15;
    int n   = (idx >> 4) & (N_ - 1);
    int b   = idx >> 16;                         // N_*16 = 65536
    int bc  = b & 3;
    int c   = __ldg(g_cl + bc * N_ + n);
    float4 v = ((const float4*)g_Vout)[(b * C_ + c) * 16 + dv];
    ((float4*)out)[idx] = v;
}

// ---------------------------------------------------------------------------
extern "C" void kernel_launch(void* const* d_in, const int* in_sizes, int n_in,
                              void* d_out, int out_size) {
    const float* Q  = (const float*)d_in[0];
    const float* K  = (const float*)d_in[1];
    const float* V  = (const float*)d_in[2];
    const void*  cl = d_in[3];
    float* out = (float*)d_out;
    float* attn_out = out + (size_t)B_ * N_ * D_;   // second output region

    prep_kernel<<<1, 256>>>(cl);
    sort_kernel<<<BC_, 256>>>();
    centers_kernel<<<dim3(B_, 4), 256>>>(Q, K, V);
    attn_kernel<<<dim3(B_, (C_ + 15) / 16), 256>>>(attn_out);
    gather_kernel<<<(B_ * N_ * (D_ / 4)) / 256, 256>>>(out);
}

// round 3
// speedup vs baseline: 1.4040x; 1.4040x over previous
#include <cuda_runtime.h>
#include <cuda_bf16.h>

#define B_   32
#define N_   4096
#define D_   64
#define BC_  4
#define C_   129

// Scratch (no allocations allowed)
__device__ __align__(16) int   g_cl[BC_ * N_];
__device__ __align__(16) int   g_order[BC_ * N_];
__device__ __align__(16) int   g_starts[BC_ * (C_ + 1)];
__device__ __align__(16) float g_Qc[B_ * C_ * D_];
__device__ __align__(16) float g_Kc[B_ * C_ * D_];
__device__ __align__(16) float g_Vc[B_ * C_ * D_];
__device__ __align__(16) float g_Vout[B_ * C_ * D_];

// ---------------------------------------------------------------------------
// Kernel 1: dtype detect + counting sort per cluster-batch (4 blocks)
// ---------------------------------------------------------------------------
__global__ void sort_kernel(const void* __restrict__ cl_raw) {
    __shared__ int s_bad;
    __shared__ int scl[N_];
    __shared__ int hist[C_];
    __shared__ int offs[C_];
    int bc = blockIdx.x;
    int t  = threadIdx.x;

    if (t == 0) s_bad = 0;
    __syncthreads();
    // int64 view of the whole buffer's first half == full buffer if int32
    const long long* c64 = (const long long*)cl_raw;
    int bad = 0;
    for (int i = t; i < (BC_ * N_) / 2; i += 256) {
        long long v = c64[i];
        if (v < 0 || v >= C_) bad = 1;
    }
    if (bad) atomicOr(&s_bad, 1);
    __syncthreads();

    if (s_bad) {
        const int* c32 = (const int*)cl_raw;
        for (int n = t; n < N_; n += 256) scl[n] = c32[bc * N_ + n];
    } else {
        for (int n = t; n < N_; n += 256) scl[n] = (int)c64[bc * N_ + n];
    }
    for (int i = t; i < C_; i += 256) hist[i] = 0;
    __syncthreads();

    for (int n = t; n < N_; n += 256) {
        g_cl[bc * N_ + n] = scl[n];
        atomicAdd(&hist[scl[n]], 1);
    }
    __syncthreads();
    if (t == 0) {
        int s = 0;
        for (int c = 0; c < C_; c++) {
            g_starts[bc * (C_ + 1) + c] = s;
            offs[c] = s;
            s += hist[c];
        }
        g_starts[bc * (C_ + 1) + C_] = s;
    }
    __syncthreads();
    for (int n = t; n < N_; n += 256) {
        int p = atomicAdd(&offs[scl[n]], 1);
        g_order[bc * N_ + p] = n;
    }
}

// ---------------------------------------------------------------------------
// Kernel 2: per-cluster centers. Warp owns a cluster; 2 members per warp-load
// (float4 lanes), 8-member unroll => 12 LDG.128 in flight. grid (32,8) x 256.
// ---------------------------------------------------------------------------
__global__ void centers_kernel(const float* __restrict__ Q,
                               const float* __restrict__ K,
                               const float* __restrict__ V) {
    int b    = blockIdx.x;
    int bc   = b & 3;
    int wid  = threadIdx.x >> 5;
    int lane = threadIdx.x & 31;
    int half = lane >> 4;      // member parity within a pair
    int dc   = lane & 15;      // float4 chunk of the 64-float row

    const float4* Qb = (const float4*)(Q + (size_t)b * N_ * D_);
    const float4* Kb = (const float4*)(K + (size_t)b * N_ * D_);
    const float4* Vb = (const float4*)(V + (size_t)b * N_ * D_);
    const int* ord = g_order + bc * N_;
    const int* sts = g_starts + bc * (C_ + 1);

    for (int c = blockIdx.y * 8 + wid; c < C_; c += 64) {
        int s0 = sts[c], s1 = sts[c + 1];
        float w = (s1 > s0) ? 1.0f / (float)(s1 - s0) : 0.0f;
        float4 aq = {0.f,0.f,0.f,0.f}, ak = aq, av = aq;

        for (int m = s0; m < s1; m += 8) {
            int   nn[4];
            float mk[4];
#pragma unroll
            for (int p = 0; p < 4; p++) {
                int mm = m + 2 * p + half;
                bool vld = mm < s1;
                nn[p] = __ldg(ord + (vld ? mm : s0));
                mk[p] = vld ? 1.0f : 0.0f;
            }
            float4 q4[4], k4[4], v4[4];
#pragma unroll
            for (int p = 0; p < 4; p++) {
                size_t off = (size_t)nn[p] * 16 + dc;
                q4[p] = Qb[off];
                k4[p] = Kb[off];
                v4[p] = Vb[off];
            }
#pragma unroll
            for (int p = 0; p < 4; p++) {
                aq.x = fmaf(mk[p], q4[p].x, aq.x); aq.y = fmaf(mk[p], q4[p].y, aq.y);
                aq.z = fmaf(mk[p], q4[p].z, aq.z); aq.w = fmaf(mk[p], q4[p].w, aq.w);
                ak.x = fmaf(mk[p], k4[p].x, ak.x); ak.y = fmaf(mk[p], k4[p].y, ak.y);
                ak.z = fmaf(mk[p], k4[p].z, ak.z); ak.w = fmaf(mk[p], k4[p].w, ak.w);
                av.x = fmaf(mk[p], v4[p].x, av.x); av.y = fmaf(mk[p], v4[p].y, av.y);
                av.z = fmaf(mk[p], v4[p].z, av.z); av.w = fmaf(mk[p], v4[p].w, av.w);
            }
        }
        // combine the two member-parity halves
        unsigned fm = 0xFFFFFFFFu;
        aq.x += __shfl_xor_sync(fm, aq.x, 16); aq.y += __shfl_xor_sync(fm, aq.y, 16);
        aq.z += __shfl_xor_sync(fm, aq.z, 16); aq.w += __shfl_xor_sync(fm, aq.w, 16);
        ak.x += __shfl_xor_sync(fm, ak.x, 16); ak.y += __shfl_xor_sync(fm, ak.y, 16);
        ak.z += __shfl_xor_sync(fm, ak.z, 16); ak.w += __shfl_xor_sync(fm, ak.w, 16);
        av.x += __shfl_xor_sync(fm, av.x, 16); av.y += __shfl_xor_sync(fm, av.y, 16);
        av.z += __shfl_xor_sync(fm, av.z, 16); av.w += __shfl_xor_sync(fm, av.w, 16);
        if (half == 0) {
            size_t o = (size_t)(b * C_ + c) * 16 + dc;
            ((float4*)g_Qc)[o] = make_float4(aq.x*w, aq.y*w, aq.z*w, aq.w*w);
            ((float4*)g_Kc)[o] = make_float4(ak.x*w, ak.y*w, ak.z*w, ak.w*w);
            ((float4*)g_Vc)[o] = make_float4(av.x*w, av.y*w, av.z*w, av.w*w);
        }
    }
}

// ---------------------------------------------------------------------------
// Kernel 3: centered attention. grid (32, 9) x 256. q-tile 16. Sync-light.
// ---------------------------------------------------------------------------
__global__ void attn_kernel(float* __restrict__ attn_out) {
    __shared__ __align__(16) float sK[C_ * 68];     // K stride 68 (17 f4); reused for V (stride 64)
    __shared__ __align__(16) float sQt[16 * 68];    // Q tile stride 68
    __shared__ __align__(16) float sP[16 * 132];    // scores/probs; reused as partial f4 buf
    __shared__ float sCnt[C_];

    int b  = blockIdx.x;
    int bc = b & 3;
    int q0 = blockIdx.y * 16;
    int t  = threadIdx.x;

    const int* sts = g_starts + bc * (C_ + 1);
    for (int k = t; k < C_; k += 256) sCnt[k] = (float)(sts[k + 1] - sts[k]);

    const float* Kc = g_Kc + (size_t)b * C_ * D_;
    for (int i = t; i < C_ * D_; i += 256) {
        int k = i >> 6, d = i & 63;
        sK[k * 68 + d] = Kc[i];
    }
    const float* Qc = g_Qc + (size_t)b * C_ * D_;
    for (int i = t; i < 16 * 64; i += 256) {
        int j = i >> 6, d = i & 63, q = q0 + j;
        sQt[j * 68 + d] = (q < C_) ? Qc[q * 64 + d] : 0.0f;
    }
    __syncthreads();

    // ---- Phase A: scores. thread = (q-quad jp4, k-slot). 4-way q blocking.
    {
        int w      = t >> 5;
        int jp4    = w >> 1;           // q rows 4*jp4 .. 4*jp4+3
        int kstart = (t & 31) + 32 * (w & 1);   // 0..63; k's = kstart, kstart+64
        const float4* sK4 = (const float4*)sK;
        const float4* sQ4 = (const float4*)sQt;
        float4 a0[4], a1[4];
#pragma unroll
        for (int qi = 0; qi < 4; qi++) { a0[qi] = make_float4(0,0,0,0); a1[qi] = a0[qi]; }
#pragma unroll
        for (int d4 = 0; d4 < 16; d4++) {
            float4 kva = sK4[kstart * 17 + d4];
            float4 kvb = sK4[(kstart + 64) * 17 + d4];
#pragma unroll
            for (int qi = 0; qi < 4; qi++) {
                float4 qv = sQ4[(4 * jp4 + qi) * 17 + d4];
                a0[qi].x = fmaf(qv.x, kva.x, a0[qi].x); a0[qi].y = fmaf(qv.y, kva.y, a0[qi].y);
                a0[qi].z = fmaf(qv.z, kva.z, a0[qi].z); a0[qi].w = fmaf(qv.w, kva.w, a0[qi].w);
                a1[qi].x = fmaf(qv.x, kvb.x, a1[qi].x); a1[qi].y = fmaf(qv.y, kvb.y, a1[qi].y);
                a1[qi].z = fmaf(qv.z, kvb.z, a1[qi].z); a1[qi].w = fmaf(qv.w, kvb.w, a1[qi].w);
            }
        }
#pragma unroll
        for (int qi = 0; qi < 4; qi++) {
            sP[(4 * jp4 + qi) * 132 + kstart]      = (a0[qi].x + a0[qi].y) + (a0[qi].z + a0[qi].w);
            sP[(4 * jp4 + qi) * 132 + kstart + 64] = (a1[qi].x + a1[qi].y) + (a1[qi].z + a1[qi].w);
        }
        if (kstart == 0) {   // epilogue column k=128 (4 threads, one per q-quad)
            float a[4] = {0.f, 0.f, 0.f, 0.f};
            for (int d = 0; d < 64; d++) {
                float kv = sK[128 * 68 + d];
#pragma unroll
                for (int qi = 0; qi < 4; qi++) a[qi] = fmaf(sQt[(4 * jp4 + qi) * 68 + d], kv, a[qi]);
            }
#pragma unroll
            for (int qi = 0; qi < 4; qi++) sP[(4 * jp4 + qi) * 132 + 128] = a[qi];
        }
    }
    __syncthreads();

    // ---- Softmax with count reweighting: one warp per q row
    {
        int wid = t >> 5, lane = t & 31;
        for (int j = wid; j < 16; j += 8) {
            float* row = &sP[j * 132];
            float v[5];
            float mx = -1e30f;
#pragma unroll
            for (int i = 0; i < 5; i++) {
                int k = lane + 32 * i;
                v[i] = (k < C_) ? row[k] : -1e30f;
                mx = fmaxf(mx, v[i]);
            }
#pragma unroll
            for (int o = 16; o; o >>= 1) mx = fmaxf(mx, __shfl_xor_sync(0xFFFFFFFFu, mx, o));
            float e[5];
            float sum = 0.f;
#pragma unroll
            for (int i = 0; i < 5; i++) {
                int k = lane + 32 * i;
                e[i] = (k < C_) ? __expf(v[i] - mx) * sCnt[k] : 0.0f;
                sum += e[i];
            }
#pragma unroll
            for (int o = 16; o; o >>= 1) sum += __shfl_xor_sync(0xFFFFFFFFu, sum, o);
            float inv = 1.0f / sum;
#pragma unroll
            for (int i = 0; i < 5; i++) {
                int k = lane + 32 * i;
                if (k < C_) row[k] = e[i] * inv;
            }
            if (lane == 0 && (q0 + j) < C_) attn_out[b * C_ + q0 + j] = e[0] * inv;
        }
    }
    __syncthreads();

    // ---- Load V (stride 64) into sK region
    const float* Vc = g_Vc + (size_t)b * C_ * D_;
    for (int i = t; i < C_ * D_; i += 256) sK[i] = Vc[i];
    __syncthreads();

    // ---- Phase B: out = P @ V. thread = (k-half, j-group, dv). No syncs in loop.
    {
        int kh2 = t >> 7;          // k parity
        int jg  = (t >> 4) & 7;    // j rows jg, jg+8
        int dv  = t & 15;          // float4 chunk
        const float4* sV4 = (const float4*)sK;
        float4 acc0 = make_float4(0,0,0,0), acc1 = acc0;
        for (int k = kh2; k < C_; k += 2) {
            float4 v  = sV4[k * 16 + dv];
            float  p0 = sP[jg * 132 + k];
            float  p1 = sP[(jg + 8) * 132 + k];
            acc0.x = fmaf(p0, v.x, acc0.x); acc0.y = fmaf(p0, v.y, acc0.y);
            acc0.z = fmaf(p0, v.z, acc0.z); acc0.w = fmaf(p0, v.w, acc0.w);
            acc1.x = fmaf(p1, v.x, acc1.x); acc1.y = fmaf(p1, v.y, acc1.y);
            acc1.z = fmaf(p1, v.z, acc1.z); acc1.w = fmaf(p1, v.w, acc1.w);
        }
        __syncthreads();           // all sP reads done
        float4* part = (float4*)sP;      // [2][16][16] float4 = 8192B
        part[(kh2 * 16 + jg) * 16 + dv]     = acc0;
        part[(kh2 * 16 + jg + 8) * 16 + dv] = acc1;
        __syncthreads();
        int jj = t >> 4;           // 0..15
        float4 r0 = part[jj * 16 + dv];
        float4 r1 = part[(16 + jj) * 16 + dv];
        if (q0 + jj < C_) {
            ((float4*)(g_Vout + (size_t)(b * C_ + q0 + jj) * D_))[dv] =
                make_float4(r0.x + r1.x, r0.y + r1.y, r0.z + r1.z, r0.w + r1.w);
        }
    }
}

// ---------------------------------------------------------------------------
// Kernel 4: gather broadcast out[b,n,:] = Vout[b, g_cl[b%4, n], :]
// ---------------------------------------------------------------------------
__global__ void gather_kernel(float* __restrict__ out) {
    int idx = blockIdx.x * 256 + threadIdx.x;   // over B*N*(D/4) float4s
    int dv  = idx & 15;
    int n   = (idx >> 4) & (N_ - 1);
    int b   = idx >> 16;
    int bc  = b & 3;
    int c   = __ldg(g_cl + bc * N_ + n);
    float4 v = ((const float4*)g_Vout)[(b * C_ + c) * 16 + dv];
    ((float4*)out)[idx] = v;
}

// ---------------------------------------------------------------------------
extern "C" void kernel_launch(void* const* d_in, const int* in_sizes, int n_in,
                              void* d_out, int out_size) {
    const float* Q  = (const float*)d_in[0];
    const float* K  = (const float*)d_in[1];
    const float* V  = (const float*)d_in[2];
    const void*  cl = d_in[3];
    float* out = (float*)d_out;
    float* attn_out = out + (size_t)B_ * N_ * D_;

    sort_kernel<<<BC_, 256>>>(cl);
    centers_kernel<<<dim3(B_, 8), 256>>>(Q, K, V);
    attn_kernel<<<dim3(B_, (C_ + 15) / 16), 256>>>(attn_out);
    gather_kernel<<<(B_ * N_ * (D_ / 4)) / 256, 256>>>(out);
}

// round 4
// speedup vs baseline: 1.4430x; 1.0277x over previous
#include <cuda_runtime.h>
#include <cuda_bf16.h>

#define B_   32
#define N_   4096
#define D_   64
#define BC_  4
#define C_   129

// Scratch (no allocations allowed)
__device__ __align__(16) int g_cl[BC_ * N_];
__device__ __align__(16) int g_order[BC_ * N_];
__device__ __align__(16) int g_starts[BC_ * (C_ + 1)];
__device__ __align__(16) float g_Qc[B_ * C_ * D_];
__device__ __align__(16) float g_Kc[B_ * C_ * D_];
__device__ __align__(16) float g_Vc[B_ * C_ * D_];

// ---------------------------------------------------------------------------
// Kernel 1: dtype detect + counting sort per cluster-batch (4 blocks)
// ---------------------------------------------------------------------------
__global__ void sort_kernel(const void* __restrict__ cl_raw) {
    __shared__ int s_bad;
    __shared__ int scl[N_];
    __shared__ int hist[256];
    __shared__ int scan[256];
    __shared__ int offs[C_];
    int bc = blockIdx.x;
    int t  = threadIdx.x;

    if (t == 0) s_bad = 0;
    hist[t] = 0;
    __syncthreads();
    // int64 view of the buffer's first half == full buffer if data is int32
    const long long* c64 = (const long long*)cl_raw;
    int bad = 0;
    for (int i = t; i < (BC_ * N_) / 2; i += 256) {
        long long v = c64[i];
        if (v < 0 || v >= C_) bad = 1;
    }
    if (bad) atomicOr(&s_bad, 1);
    __syncthreads();

    if (s_bad) {
        const int* c32 = (const int*)cl_raw;
        for (int n = t; n < N_; n += 256) scl[n] = c32[bc * N_ + n];
    } else {
        for (int n = t; n < N_; n += 256) scl[n] = (int)c64[bc * N_ + n];
    }
    __syncthreads();

    for (int n = t; n < N_; n += 256) {
        g_cl[bc * N_ + n] = scl[n];
        atomicAdd(&hist[scl[n]], 1);
    }
    __syncthreads();

    // Hillis-Steele inclusive scan over 256 bins
    int val = hist[t];
    scan[t] = val;
    __syncthreads();
#pragma unroll
    for (int off = 1; off < 256; off <<= 1) {
        int v = (t >= off) ? scan[t - off] : 0;
        __syncthreads();
        scan[t] += v;
        __syncthreads();
    }
    int excl = scan[t] - val;
    if (t < C_) {
        g_starts[bc * (C_ + 1) + t] = excl;
        offs[t] = excl;
    }
    if (t == C_ - 1) g_starts[bc * (C_ + 1) + C_] = scan[t];
    __syncthreads();

    for (int n = t; n < N_; n += 256) {
        int p = atomicAdd(&offs[scl[n]], 1);
        g_order[bc * N_ + p] = n;
    }
}

// ---------------------------------------------------------------------------
// Kernel 2: per-cluster centers. Warp owns a cluster; 2 members per warp-load
// (float4 lanes), 12-member unroll => 18 LDG.128 in flight. grid (32,8) x 256.
// ---------------------------------------------------------------------------
__global__ void centers_kernel(const float* __restrict__ Q,
                               const float* __restrict__ K,
                               const float* __restrict__ V) {
    int b    = blockIdx.x;
    int bc   = b & 3;
    int wid  = threadIdx.x >> 5;
    int lane = threadIdx.x & 31;
    int half = lane >> 4;      // member parity within a pair
    int dc   = lane & 15;      // float4 chunk of the 64-float row

    const float4* Qb = (const float4*)(Q + (size_t)b * N_ * D_);
    const float4* Kb = (const float4*)(K + (size_t)b * N_ * D_);
    const float4* Vb = (const float4*)(V + (size_t)b * N_ * D_);
    const int* ord = g_order + bc * N_;
    const int* sts = g_starts + bc * (C_ + 1);

    for (int c = blockIdx.y * 8 + wid; c < C_; c += 64) {
        int s0 = sts[c], s1 = sts[c + 1];
        float w = (s1 > s0) ? 1.0f / (float)(s1 - s0) : 0.0f;
        float4 aq = {0.f,0.f,0.f,0.f}, ak = aq, av = aq;

        for (int m = s0; m < s1; m += 12) {
            int   nn[6];
            float mk[6];
#pragma unroll
            for (int p = 0; p < 6; p++) {
                int mm = m + 2 * p + half;
                bool vld = mm < s1;
                nn[p] = __ldg(ord + (vld ? mm : s0));
                mk[p] = vld ? 1.0f : 0.0f;
            }
            float4 q4[6], k4[6], v4[6];
#pragma unroll
            for (int p = 0; p < 6; p++) {
                size_t off = (size_t)nn[p] * 16 + dc;
                q4[p] = Qb[off];
                k4[p] = Kb[off];
                v4[p] = Vb[off];
            }
#pragma unroll
            for (int p = 0; p < 6; p++) {
                aq.x = fmaf(mk[p], q4[p].x, aq.x); aq.y = fmaf(mk[p], q4[p].y, aq.y);
                aq.z = fmaf(mk[p], q4[p].z, aq.z); aq.w = fmaf(mk[p], q4[p].w, aq.w);
                ak.x = fmaf(mk[p], k4[p].x, ak.x); ak.y = fmaf(mk[p], k4[p].y, ak.y);
                ak.z = fmaf(mk[p], k4[p].z, ak.z); ak.w = fmaf(mk[p], k4[p].w, ak.w);
                av.x = fmaf(mk[p], v4[p].x, av.x); av.y = fmaf(mk[p], v4[p].y, av.y);
                av.z = fmaf(mk[p], v4[p].z, av.z); av.w = fmaf(mk[p], v4[p].w, av.w);
            }
        }
        // combine the two member-parity halves
        unsigned fm = 0xFFFFFFFFu;
        aq.x += __shfl_xor_sync(fm, aq.x, 16); aq.y += __shfl_xor_sync(fm, aq.y, 16);
        aq.z += __shfl_xor_sync(fm, aq.z, 16); aq.w += __shfl_xor_sync(fm, aq.w, 16);
        ak.x += __shfl_xor_sync(fm, ak.x, 16); ak.y += __shfl_xor_sync(fm, ak.y, 16);
        ak.z += __shfl_xor_sync(fm, ak.z, 16); ak.w += __shfl_xor_sync(fm, ak.w, 16);
        av.x += __shfl_xor_sync(fm, av.x, 16); av.y += __shfl_xor_sync(fm, av.y, 16);
        av.z += __shfl_xor_sync(fm, av.z, 16); av.w += __shfl_xor_sync(fm, av.w, 16);
        if (half == 0) {
            size_t o = (size_t)(b * C_ + c) * 16 + dc;
            ((float4*)g_Qc)[o] = make_float4(aq.x*w, aq.y*w, aq.z*w, aq.w*w);
            ((float4*)g_Kc)[o] = make_float4(ak.x*w, ak.y*w, ak.z*w, ak.w*w);
            ((float4*)g_Vc)[o] = make_float4(av.x*w, av.y*w, av.z*w, av.w*w);
        }
    }
}

// ---------------------------------------------------------------------------
// Kernel 3: centered attention + direct member broadcast. grid (32,9) x 256.
// ---------------------------------------------------------------------------
__global__ void attn_kernel(float* __restrict__ out, float* __restrict__ attn_out) {
    __shared__ __align__(16) float sK[C_ * 68];     // K stride 68 (17 f4); reused for V (stride 64)
    __shared__ __align__(16) float sQt[16 * 68];    // Q tile stride 68; reused as sOut
    __shared__ __align__(16) float sP[16 * 132];    // scores/probs; reused as partial f4 buf
    __shared__ float sCnt[C_];

    int b  = blockIdx.x;
    int bc = b & 3;
    int q0 = blockIdx.y * 16;
    int t  = threadIdx.x;

    const int* sts = g_starts + bc * (C_ + 1);
    const int* ord = g_order + bc * N_;
    for (int k = t; k < C_; k += 256) sCnt[k] = (float)(sts[k + 1] - sts[k]);

    const float* Kc = g_Kc + (size_t)b * C_ * D_;
    for (int i = t; i < C_ * D_; i += 256) {
        int k = i >> 6, d = i & 63;
        sK[k * 68 + d] = Kc[i];
    }
    const float* Qc = g_Qc + (size_t)b * C_ * D_;
    for (int i = t; i < 16 * 64; i += 256) {
        int j = i >> 6, d = i & 63, q = q0 + j;
        sQt[j * 68 + d] = (q < C_) ? Qc[q * 64 + d] : 0.0f;
    }
    __syncthreads();

    // ---- Phase A: scores. thread = (q-quad jp4, k-slot). 4-way q blocking.
    {
        int w      = t >> 5;
        int jp4    = w >> 1;
        int kstart = (t & 31) + 32 * (w & 1);
        const float4* sK4 = (const float4*)sK;
        const float4* sQ4 = (const float4*)sQt;
        float4 a0[4], a1[4];
#pragma unroll
        for (int qi = 0; qi < 4; qi++) { a0[qi] = make_float4(0,0,0,0); a1[qi] = a0[qi]; }
#pragma unroll
        for (int d4 = 0; d4 < 16; d4++) {
            float4 kva = sK4[kstart * 17 + d4];
            float4 kvb = sK4[(kstart + 64) * 17 + d4];
#pragma unroll
            for (int qi = 0; qi < 4; qi++) {
                float4 qv = sQ4[(4 * jp4 + qi) * 17 + d4];
                a0[qi].x = fmaf(qv.x, kva.x, a0[qi].x); a0[qi].y = fmaf(qv.y, kva.y, a0[qi].y);
                a0[qi].z = fmaf(qv.z, kva.z, a0[qi].z); a0[qi].w = fmaf(qv.w, kva.w, a0[qi].w);
                a1[qi].x = fmaf(qv.x, kvb.x, a1[qi].x); a1[qi].y = fmaf(qv.y, kvb.y, a1[qi].y);
                a1[qi].z = fmaf(qv.z, kvb.z, a1[qi].z); a1[qi].w = fmaf(qv.w, kvb.w, a1[qi].w);
            }
        }
#pragma unroll
        for (int qi = 0; qi < 4; qi++) {
            sP[(4 * jp4 + qi) * 132 + kstart]      = (a0[qi].x + a0[qi].y) + (a0[qi].z + a0[qi].w);
            sP[(4 * jp4 + qi) * 132 + kstart + 64] = (a1[qi].x + a1[qi].y) + (a1[qi].z + a1[qi].w);
        }
        if (kstart == 0) {   // epilogue column k=128
            float a[4] = {0.f, 0.f, 0.f, 0.f};
            for (int d = 0; d < 64; d++) {
                float kv = sK[128 * 68 + d];
#pragma unroll
                for (int qi = 0; qi < 4; qi++) a[qi] = fmaf(sQt[(4 * jp4 + qi) * 68 + d], kv, a[qi]);
            }
#pragma unroll
            for (int qi = 0; qi < 4; qi++) sP[(4 * jp4 + qi) * 132 + 128] = a[qi];
        }
    }
    __syncthreads();

    // ---- Softmax with count reweighting: one warp per q row
    {
        int wid = t >> 5, lane = t & 31;
        for (int j = wid; j < 16; j += 8) {
            float* row = &sP[j * 132];
            float v[5];
            float mx = -1e30f;
#pragma unroll
            for (int i = 0; i < 5; i++) {
                int k = lane + 32 * i;
                v[i] = (k < C_) ? row[k] : -1e30f;
                mx = fmaxf(mx, v[i]);
            }
#pragma unroll
            for (int o = 16; o; o >>= 1) mx = fmaxf(mx, __shfl_xor_sync(0xFFFFFFFFu, mx, o));
            float e[5];
            float sum = 0.f;
#pragma unroll
            for (int i = 0; i < 5; i++) {
                int k = lane + 32 * i;
                e[i] = (k < C_) ? __expf(v[i] - mx) * sCnt[k] : 0.0f;
                sum += e[i];
            }
#pragma unroll
            for (int o = 16; o; o >>= 1) sum += __shfl_xor_sync(0xFFFFFFFFu, sum, o);
            float inv = 1.0f / sum;
#pragma unroll
            for (int i = 0; i < 5; i++) {
                int k = lane + 32 * i;
                if (k < C_) row[k] = e[i] * inv;
            }
            if (lane == 0 && (q0 + j) < C_) attn_out[b * C_ + q0 + j] = e[0] * inv;
        }
    }
    __syncthreads();

    // ---- Load V (stride 64) into sK region
    const float* Vc = g_Vc + (size_t)b * C_ * D_;
    for (int i = t; i < C_ * D_; i += 256) sK[i] = Vc[i];
    __syncthreads();

    // ---- Phase B: out = P @ V, then direct broadcast to members.
    {
        int kh2 = t >> 7;          // k parity
        int jg  = (t >> 4) & 7;    // j rows jg, jg+8
        int dv  = t & 15;          // float4 chunk
        const float4* sV4 = (const float4*)sK;
        float4 acc0 = make_float4(0,0,0,0), acc1 = acc0;
        for (int k = kh2; k < C_; k += 2) {
            float4 v  = sV4[k * 16 + dv];
            float  p0 = sP[jg * 132 + k];
            float  p1 = sP[(jg + 8) * 132 + k];
            acc0.x = fmaf(p0, v.x, acc0.x); acc0.y = fmaf(p0, v.y, acc0.y);
            acc0.z = fmaf(p0, v.z, acc0.z); acc0.w = fmaf(p0, v.w, acc0.w);
            acc1.x = fmaf(p1, v.x, acc1.x); acc1.y = fmaf(p1, v.y, acc1.y);
            acc1.z = fmaf(p1, v.z, acc1.z); acc1.w = fmaf(p1, v.w, acc1.w);
        }
        __syncthreads();           // all sP reads done
        float4* part = (float4*)sP;      // [2][16][16] float4 = 8192B
        part[(kh2 * 16 + jg) * 16 + dv]     = acc0;
        part[(kh2 * 16 + jg + 8) * 16 + dv] = acc1;
        __syncthreads();
        int jj = t >> 4;           // 0..15
        float4 r0 = part[jj * 16 + dv];
        float4 r1 = part[(16 + jj) * 16 + dv];
        float4* sOut4 = (float4*)sQt;    // reuse dead Q-tile buffer
        sOut4[jj * 16 + dv] = make_float4(r0.x + r1.x, r0.y + r1.y, r0.z + r1.z, r0.w + r1.w);
        __syncthreads();

        // Broadcast each cluster's output row to all its members
        int rowSlot = t >> 4;      // 0..15: member slot within an iteration
        for (int j = 0; j < 16; j++) {
            int q = q0 + j;
            if (q >= C_) break;
            int s0 = sts[q], cnt = sts[q + 1] - s0;
            float4 val = sOut4[j * 16 + dv];
            for (int m = rowSlot; m < cnt; m += 16) {
                int n = __ldg(ord + s0 + m);
                ((float4*)(out + ((size_t)b * N_ + n) * D_))[dv] = val;
            }
        }
    }
}

// ---------------------------------------------------------------------------
extern "C" void kernel_launch(void* const* d_in, const int* in_sizes, int n_in,
                              void* d_out, int out_size) {
    const float* Q  = (const float*)d_in[0];
    const float* K  = (const float*)d_in[1];
    const float* V  = (const float*)d_in[2];
    const void*  cl = d_in[3];
    float* out = (float*)d_out;
    float* attn_out = out + (size_t)B_ * N_ * D_;

    sort_kernel<<<BC_, 256>>>(cl);
    centers_kernel<<<dim3(B_, 8), 256>>>(Q, K, V);
    attn_kernel<<<dim3(B_, (C_ + 15) / 16), 256>>>(out, attn_out);
}